// round 7
// baseline (speedup 1.0000x reference)
#include <cuda_runtime.h>
#include <cuda_bf16.h>
#include <mma.h>
#include <cstdint>

using namespace nvcuda;
typedef __nv_bfloat16  bf16;
typedef __nv_bfloat162 bf162;

// Problem constants
#define Bsz 16384
#define Dd  1024
#define Lc  6
#define NMC 64
#define Hh  16
#define M1  (1024 * 1024)
#define BD  ((size_t)Bsz * Dd)

// Tiling: generic block 256x128, fused block 256x64, 8 warps, 3-stage cp.async
#define BK   32
#define LDK  40
#define GSTGB ((256 + 256 + 128 + 128) * LDK * 2)   // 61440 B/stage
#define FSTGB ((256 + 256 + 64 * 4) * LDK * 2)      // 61440 B/stage
#define GDSM (3 * GSTGB)                            // 184320
#define FDSM (3 * FSTGB)                            // 184320
#define NKT  (Dd / BK)                              // 32

// ---------------------------------------------------------------------------
// Persistent buffers
// ---------------------------------------------------------------------------
__device__ bf16 g_wc_h [6 * M1], g_wc_l [6 * M1];   // combo weights, [n][k]
__device__ bf16 g_wv_h [6 * M1], g_wv_l [6 * M1];
__device__ bf16 g_wo_h [6 * M1], g_wo_l [6 * M1];
__device__ bf16 g_fb_h [5 * M1], g_fb_l [5 * M1];
__device__ bf16 g_we_h [6 * M1], g_we_l [6 * M1];   // gathered [n=m*16+h][k=d]
__device__ bf16 g_wi_h [6 * M1], g_wi_l [6 * M1];
__device__ bf16 g_s1h[6 * M1], g_s1l[6 * M1];
__device__ bf16 g_s2h[6 * M1], g_s2l[6 * M1];
__device__ float g_t2[6 * M1];
__device__ float g_bc1[6 * Dd], g_bc2[6 * Dd];
__device__ float g_zero[Dd];
__device__ bf16 g_a0h[BD], g_a0l[BD], g_a1h[BD], g_a1l[BD];

__device__ __forceinline__ void split1(float v, bf16* h, bf16* l) {
    bf16 hh = __float2bfloat16(v);
    *h = hh;
    *l = __float2bfloat16(v - __bfloat162float(hh));
}

__device__ __forceinline__ void cp16(void* smem, const void* g) {
    uint32_t s = (uint32_t)__cvta_generic_to_shared(smem);
    asm volatile("cp.async.cg.shared.global [%0], [%1], 16;" :: "r"(s), "l"(g));
}
__device__ __forceinline__ void cp_commit() { asm volatile("cp.async.commit_group;"); }
template <int N>
__device__ __forceinline__ void cp_wait() {
    asm volatile("cp.async.wait_group %0;" :: "n"(N));
}

// ---------------------------------------------------------------------------
// Conversion kernels
// ---------------------------------------------------------------------------
__global__ void conv_T(const float* __restrict__ src, bf16* __restrict__ hi,
                       bf16* __restrict__ lo) {
    __shared__ float t[32][33];
    const int l = blockIdx.z;
    const int k0 = blockIdx.y * 32, n0 = blockIdx.x * 32;
    const float* S = src + (size_t)l * M1;
    const int r = threadIdx.x >> 5, c = threadIdx.x & 31;
    #pragma unroll
    for (int i = 0; i < 4; i++)
        t[r + i * 8][c] = S[(size_t)(k0 + r + i * 8) * Dd + n0 + c];
    __syncthreads();
    bf16* H = hi + (size_t)l * M1;
    bf16* L = lo + (size_t)l * M1;
    #pragma unroll
    for (int i = 0; i < 4; i++) {
        bf16 hb, lb; split1(t[c][r + i * 8], &hb, &lb);
        size_t o = (size_t)(n0 + r + i * 8) * Dd + k0 + c;
        H[o] = hb; L[o] = lb;
    }
}

// out[l][m*16+h][d] = src[l][m][d][h]
__global__ void conv_gT(const float* __restrict__ src, bf16* __restrict__ hi,
                        bf16* __restrict__ lo) {
    __shared__ float t[64][17];
    const int d0 = blockIdx.x * 64, m = blockIdx.y, l = blockIdx.z;
    const int tid = threadIdx.x;
    {
        int dd = tid >> 2, h4 = (tid & 3) * 4;
        float4 v = *reinterpret_cast<const float4*>(
            &src[((size_t)(l * NMC + m) * Dd + d0 + dd) * Hh + h4]);
        t[dd][h4] = v.x; t[dd][h4 + 1] = v.y; t[dd][h4 + 2] = v.z; t[dd][h4 + 3] = v.w;
    }
    __syncthreads();
    int h = tid >> 4, cq = tid & 15;
    size_t rowo = (size_t)l * M1 + (size_t)(m * 16 + h) * Dd + d0 + cq * 4;
    #pragma unroll
    for (int j = 0; j < 4; j++) {
        bf16 hb, lb; split1(t[cq * 4 + j][h], &hb, &lb);
        hi[rowo + j] = hb; lo[rowo + j] = lb;
    }
}

__global__ void conv_act(const float* __restrict__ src, bf16* __restrict__ hi,
                         bf16* __restrict__ lo) {
    size_t i = ((size_t)blockIdx.x * blockDim.x + threadIdx.x) * 4;
    float4 v = *reinterpret_cast<const float4*>(src + i);
    bf16 hs[4], ls[4];
    split1(v.x, &hs[0], &ls[0]); split1(v.y, &hs[1], &ls[1]);
    split1(v.z, &hs[2], &ls[2]); split1(v.w, &hs[3], &ls[3]);
    *reinterpret_cast<float2*>(hi + i) = *reinterpret_cast<float2*>(hs);
    *reinterpret_cast<float2*>(lo + i) = *reinterpret_cast<float2*>(ls);
}

// bc[l][j] = sum_i bin[l][i] * W[l][i][j] + badd[l][j]
__global__ void bias_combo(const float* __restrict__ bin, const float* __restrict__ W,
                           const float* __restrict__ badd, float* __restrict__ bc) {
    const int l = blockIdx.y;
    const int j = blockIdx.x * 256 + threadIdx.x;
    const float* Wl = W + (size_t)l * M1;
    const float* bi = bin + (size_t)l * Dd;
    float s = badd[(size_t)l * Dd + j];
    for (int i = 0; i < Dd; i++) s += bi[i] * Wl[(size_t)i * Dd + j];
    bc[(size_t)l * Dd + j] = s;
}

// ---------------------------------------------------------------------------
// GEMM: C = (ACC ? Cf : 0) + A @ W + bias. Block 256x128, 8 warps, warp 64x64.
// 3-stage cp.async. z-batched via strides.
// ---------------------------------------------------------------------------
template <bool ACC, bool WF32, bool WSPLIT>
__global__ __launch_bounds__(256, 1)
void gemm_w(const bf16* __restrict__ Ahi_, const bf16* __restrict__ Alo_,
            const bf16* __restrict__ Whi_, const bf16* __restrict__ Wlo_,
            const float* __restrict__ bias_, float* __restrict__ Cf_,
            bf16* __restrict__ Chi_, bf16* __restrict__ Clo_,
            size_t sA, size_t sW, size_t sB, size_t sC) {
    extern __shared__ char smraw[];
    const int z = blockIdx.z;
    const bf16* Ahi = Ahi_ + (size_t)z * sA;
    const bf16* Alo = Alo_ + (size_t)z * sA;
    const bf16* Whi = Whi_ + (size_t)z * sW;
    const bf16* Wlo = Wlo_ + (size_t)z * sW;
    const float* bias = bias_ + (size_t)z * sB;
    float* Cf = WF32 ? Cf_ + (size_t)z * sC : nullptr;
    bf16* Chi = WSPLIT ? Chi_ + (size_t)z * sC : nullptr;
    bf16* Clo = WSPLIT ? Clo_ + (size_t)z * sC : nullptr;

    const int tid = threadIdx.x, wid = tid >> 5, lane = tid & 31;
    const int wm = wid >> 1, wn = wid & 1;
    const int m0 = blockIdx.y * 256, n0 = blockIdx.x * 128;

    wmma::fragment<wmma::accumulator, 16, 16, 16, float> acc[4][4];
    #pragma unroll
    for (int i = 0; i < 4; i++)
        #pragma unroll
        for (int j = 0; j < 4; j++)
            wmma::fill_fragment(acc[i][j], 0.0f);

    auto load_stage = [&](int st, int kt) {
        bf16* Ah = reinterpret_cast<bf16*>(smraw + st * GSTGB);
        bf16* Al = Ah + 256 * LDK;
        bf16* Bh = Al + 256 * LDK;
        bf16* Bl = Bh + 128 * LDK;
        const int k0 = kt * BK;
        #pragma unroll
        for (int t = 0; t < 4; t++) {
            int item = tid + t * 256;
            int r = item >> 2, c = (item & 3) * 8;
            size_t ga = (size_t)(m0 + r) * Dd + k0 + c;
            cp16(Ah + r * LDK + c, Ahi + ga);
            cp16(Al + r * LDK + c, Alo + ga);
        }
        #pragma unroll
        for (int t = 0; t < 2; t++) {
            int item = tid + t * 256;
            int r = item >> 2, c = (item & 3) * 8;
            size_t gb = (size_t)(n0 + r) * Dd + k0 + c;
            cp16(Bh + r * LDK + c, Whi + gb);
            cp16(Bl + r * LDK + c, Wlo + gb);
        }
        cp_commit();
    };

    load_stage(0, 0);
    load_stage(1, 1);
    for (int kt = 0; kt < NKT; kt++) {
        int st = kt % 3;
        if (kt + 2 < NKT) { load_stage((kt + 2) % 3, kt + 2); cp_wait<2>(); }
        else if (kt + 1 < NKT) { cp_wait<1>(); }
        else { cp_wait<0>(); }
        __syncthreads();

        bf16* Ah = reinterpret_cast<bf16*>(smraw + st * GSTGB);
        bf16* Al = Ah + 256 * LDK;
        bf16* Bh = Al + 256 * LDK;
        bf16* Bl = Bh + 128 * LDK;
        #pragma unroll
        for (int ks = 0; ks < BK; ks += 16) {
            wmma::fragment<wmma::matrix_b, 16, 16, 16, bf16, wmma::col_major> bh[4], bl[4];
            #pragma unroll
            for (int j = 0; j < 4; j++) {
                wmma::load_matrix_sync(bh[j], &Bh[(wn * 64 + j * 16) * LDK + ks], LDK);
                wmma::load_matrix_sync(bl[j], &Bl[(wn * 64 + j * 16) * LDK + ks], LDK);
            }
            #pragma unroll
            for (int i = 0; i < 4; i++) {
                wmma::fragment<wmma::matrix_a, 16, 16, 16, bf16, wmma::row_major> ah, al;
                wmma::load_matrix_sync(ah, &Ah[(wm * 64 + i * 16) * LDK + ks], LDK);
                wmma::load_matrix_sync(al, &Al[(wm * 64 + i * 16) * LDK + ks], LDK);
                #pragma unroll
                for (int j = 0; j < 4; j++) {
                    wmma::mma_sync(acc[i][j], ah, bh[j], acc[i][j]);
                    wmma::mma_sync(acc[i][j], ah, bl[j], acc[i][j]);
                    wmma::mma_sync(acc[i][j], al, bh[j], acc[i][j]);
                }
            }
        }
        __syncthreads();
    }

    __syncthreads();
    float* patch = reinterpret_cast<float*>(smraw) + wid * 16 * 20;
    const int er = lane >> 1, eh = (lane & 1) * 8;
    #pragma unroll
    for (int i = 0; i < 4; i++) {
        #pragma unroll
        for (int j = 0; j < 4; j++) {
            wmma::store_matrix_sync(patch, acc[i][j], 20, wmma::mem_row_major);
            __syncwarp();
            int gr = m0 + wm * 64 + i * 16 + er;
            int gc = n0 + wn * 64 + j * 16 + eh;
            size_t go = (size_t)gr * Dd + gc;
            float4 b0 = *reinterpret_cast<const float4*>(&bias[gc]);
            float4 b1 = *reinterpret_cast<const float4*>(&bias[gc + 4]);
            float v[8];
            #pragma unroll
            for (int e = 0; e < 8; e++) v[e] = patch[er * 20 + eh + e];
            v[0] += b0.x; v[1] += b0.y; v[2] += b0.z; v[3] += b0.w;
            v[4] += b1.x; v[5] += b1.y; v[6] += b1.z; v[7] += b1.w;
            if (ACC) {
                float4 o0 = *reinterpret_cast<const float4*>(&Cf[go]);
                float4 o1 = *reinterpret_cast<const float4*>(&Cf[go + 4]);
                v[0] += o0.x; v[1] += o0.y; v[2] += o0.z; v[3] += o0.w;
                v[4] += o1.x; v[5] += o1.y; v[6] += o1.z; v[7] += o1.w;
            }
            if (WF32) {
                *reinterpret_cast<float4*>(&Cf[go])     = *reinterpret_cast<float4*>(&v[0]);
                *reinterpret_cast<float4*>(&Cf[go + 4]) = *reinterpret_cast<float4*>(&v[4]);
            }
            if (WSPLIT) {
                bf16 hs[8], ls[8];
                #pragma unroll
                for (int e = 0; e < 8; e++) split1(v[e], &hs[e], &ls[e]);
                *reinterpret_cast<float4*>(&Chi[go]) = *reinterpret_cast<float4*>(hs);
                *reinterpret_cast<float4*>(&Clo[go]) = *reinterpret_cast<float4*>(ls);
            }
            __syncwarp();
        }
    }
}

// ---------------------------------------------------------------------------
// Fused minicolumn kernel: block 256x64, 8 warps, warp 64x32 (e and i), 3-stage
// ---------------------------------------------------------------------------
__global__ __launch_bounds__(256, 1)
void fused_w(const bf16* __restrict__ Ahi, const bf16* __restrict__ Alo,
             const bf16* __restrict__ Weh, const bf16* __restrict__ Wel,
             const bf16* __restrict__ Wih, const bf16* __restrict__ Wil,
             const float* __restrict__ be_l, const float* __restrict__ bi_l,
             const float* __restrict__ Wl_l, const float* __restrict__ bl_l,
             bf16* __restrict__ Mhi, bf16* __restrict__ Mlo) {
    extern __shared__ char smraw[];
    __shared__ float swl[1024];
    __shared__ float sbe[64], sbi[64], sbl[64];

    const int tid = threadIdx.x, wid = tid >> 5, lane = tid & 31;
    const int wm = wid >> 1, wn = wid & 1;
    const int m0 = blockIdx.y * 256, n0 = blockIdx.x * 64;

    for (int i = tid; i < 256; i += 256)
        *reinterpret_cast<float4*>(&swl[i * 4]) =
            *reinterpret_cast<const float4*>(&Wl_l[(size_t)n0 * Hh + i * 4]);
    if (tid < 64) {
        sbe[tid] = be_l[n0 + tid];
        sbi[tid] = bi_l[n0 + tid];
        sbl[tid] = bl_l[n0 + tid];
    }

    wmma::fragment<wmma::accumulator, 16, 16, 16, float> ae[4][2], ai[4][2];
    #pragma unroll
    for (int i = 0; i < 4; i++)
        #pragma unroll
        for (int j = 0; j < 2; j++) {
            wmma::fill_fragment(ae[i][j], 0.0f);
            wmma::fill_fragment(ai[i][j], 0.0f);
        }

    auto load_stage = [&](int st, int kt) {
        bf16* Ah = reinterpret_cast<bf16*>(smraw + st * FSTGB);
        bf16* Al = Ah + 256 * LDK;
        bf16* Eh = Al + 256 * LDK;
        bf16* El = Eh + 64 * LDK;
        bf16* Ih = El + 64 * LDK;
        bf16* Il = Ih + 64 * LDK;
        const int k0 = kt * BK;
        #pragma unroll
        for (int t = 0; t < 4; t++) {
            int item = tid + t * 256;
            int r = item >> 2, c = (item & 3) * 8;
            size_t ga = (size_t)(m0 + r) * Dd + k0 + c;
            cp16(Ah + r * LDK + c, Ahi + ga);
            cp16(Al + r * LDK + c, Alo + ga);
        }
        {
            int r = tid >> 2, c = (tid & 3) * 8;
            if (r < 64) {
                size_t gb = (size_t)(n0 + r) * Dd + k0 + c;
                cp16(Eh + r * LDK + c, Weh + gb);
                cp16(El + r * LDK + c, Wel + gb);
                cp16(Ih + r * LDK + c, Wih + gb);
                cp16(Il + r * LDK + c, Wil + gb);
            }
        }
        cp_commit();
    };

    load_stage(0, 0);
    load_stage(1, 1);
    for (int kt = 0; kt < NKT; kt++) {
        int st = kt % 3;
        if (kt + 2 < NKT) { load_stage((kt + 2) % 3, kt + 2); cp_wait<2>(); }
        else if (kt + 1 < NKT) { cp_wait<1>(); }
        else { cp_wait<0>(); }
        __syncthreads();

        bf16* Ah = reinterpret_cast<bf16*>(smraw + st * FSTGB);
        bf16* Al = Ah + 256 * LDK;
        bf16* Eh = Al + 256 * LDK;
        bf16* El = Eh + 64 * LDK;
        bf16* Ih = El + 64 * LDK;
        bf16* Il = Ih + 64 * LDK;
        #pragma unroll
        for (int ks = 0; ks < BK; ks += 16) {
            wmma::fragment<wmma::matrix_b, 16, 16, 16, bf16, wmma::col_major>
                eh[2], el[2], ih[2], il[2];
            #pragma unroll
            for (int j = 0; j < 2; j++) {
                int nb = (wn * 32 + j * 16) * LDK + ks;
                wmma::load_matrix_sync(eh[j], &Eh[nb], LDK);
                wmma::load_matrix_sync(el[j], &El[nb], LDK);
                wmma::load_matrix_sync(ih[j], &Ih[nb], LDK);
                wmma::load_matrix_sync(il[j], &Il[nb], LDK);
            }
            #pragma unroll
            for (int i = 0; i < 4; i++) {
                wmma::fragment<wmma::matrix_a, 16, 16, 16, bf16, wmma::row_major> ah, al;
                wmma::load_matrix_sync(ah, &Ah[(wm * 64 + i * 16) * LDK + ks], LDK);
                wmma::load_matrix_sync(al, &Al[(wm * 64 + i * 16) * LDK + ks], LDK);
                #pragma unroll
                for (int j = 0; j < 2; j++) {
                    wmma::mma_sync(ae[i][j], ah, eh[j], ae[i][j]);
                    wmma::mma_sync(ae[i][j], ah, el[j], ae[i][j]);
                    wmma::mma_sync(ae[i][j], al, eh[j], ae[i][j]);
                    wmma::mma_sync(ai[i][j], ah, ih[j], ai[i][j]);
                    wmma::mma_sync(ai[i][j], ah, il[j], ai[i][j]);
                    wmma::mma_sync(ai[i][j], al, ih[j], ai[i][j]);
                }
            }
        }
        __syncthreads();
    }

    __syncthreads();
    float* pe = reinterpret_cast<float*>(smraw) + wid * 2 * 16 * 20;
    float* pi = pe + 16 * 20;
    const int er = lane >> 1, eh8 = (lane & 1) * 8;
    #pragma unroll
    for (int i = 0; i < 4; i++) {
        #pragma unroll
        for (int j = 0; j < 2; j++) {
            wmma::store_matrix_sync(pe, ae[i][j], 20, wmma::mem_row_major);
            wmma::store_matrix_sync(pi, ai[i][j], 20, wmma::mem_row_major);
            __syncwarp();
            int ml = wn * 2 + j;
            int gr = m0 + wm * 64 + i * 16 + er;
            float ihv[16];
            #pragma unroll
            for (int h = 0; h < 16; h++)
                ihv[h] = fmaxf(pi[er * 20 + h] + sbi[ml * 16 + h], 0.0f);
            bf16 hs[8], ls[8];
            #pragma unroll
            for (int e = 0; e < 8; e++) {
                int k = eh8 + e;
                float lat = sbl[ml * 16 + k];
                #pragma unroll
                for (int h = 0; h < 16; h++)
                    lat += ihv[h] * swl[ml * 256 + h * 16 + k];
                float ex = fmaxf(pe[er * 20 + k] + sbe[ml * 16 + k], 0.0f);
                split1(fmaxf(ex - lat, 0.0f), &hs[e], &ls[e]);
            }
            size_t go = (size_t)gr * Dd + n0 + ml * 16 + eh8;
            *reinterpret_cast<float4*>(&Mhi[go]) = *reinterpret_cast<float4*>(hs);
            *reinterpret_cast<float4*>(&Mlo[go]) = *reinterpret_cast<float4*>(ls);
            __syncwarp();
        }
    }
}

// ---------------------------------------------------------------------------
// Host orchestration
// ---------------------------------------------------------------------------
extern "C" void kernel_launch(void* const* d_in, const int* in_sizes, int n_in,
                              void* d_out, int out_size) {
    const float* x    = (const float*)d_in[0];
    const float* We   = (const float*)d_in[1];
    const float* be   = (const float*)d_in[2];
    const float* Wi   = (const float*)d_in[3];
    const float* bi   = (const float*)d_in[4];
    const float* Wl   = (const float*)d_in[5];
    const float* bl   = (const float*)d_in[6];
    const float* Wlat = (const float*)d_in[7];
    const float* blat = (const float*)d_in[8];
    const float* Wv   = (const float*)d_in[9];
    const float* bv   = (const float*)d_in[10];
    const float* Wo   = (const float*)d_in[11];
    const float* bo   = (const float*)d_in[12];
    const float* fbW  = (const float*)d_in[13];
    const float* fbb  = (const float*)d_in[14];
    float* out = (float*)d_out;

    bf16 *wc_h, *wc_l, *wv_h, *wv_l, *wo_h, *wo_l, *fb_h, *fb_l;
    bf16 *we_h, *we_l, *wi_h, *wi_l, *a0h, *a0l, *a1h, *a1l;
    bf16 *s1h, *s1l, *s2h, *s2l;
    float *t2, *bc1, *bc2, *zero;
    cudaGetSymbolAddress((void**)&wc_h, g_wc_h);
    cudaGetSymbolAddress((void**)&wc_l, g_wc_l);
    cudaGetSymbolAddress((void**)&wv_h, g_wv_h);
    cudaGetSymbolAddress((void**)&wv_l, g_wv_l);
    cudaGetSymbolAddress((void**)&wo_h, g_wo_h);
    cudaGetSymbolAddress((void**)&wo_l, g_wo_l);
    cudaGetSymbolAddress((void**)&fb_h, g_fb_h);
    cudaGetSymbolAddress((void**)&fb_l, g_fb_l);
    cudaGetSymbolAddress((void**)&we_h, g_we_h);
    cudaGetSymbolAddress((void**)&we_l, g_we_l);
    cudaGetSymbolAddress((void**)&wi_h, g_wi_h);
    cudaGetSymbolAddress((void**)&wi_l, g_wi_l);
    cudaGetSymbolAddress((void**)&a0h,  g_a0h);
    cudaGetSymbolAddress((void**)&a0l,  g_a0l);
    cudaGetSymbolAddress((void**)&a1h,  g_a1h);
    cudaGetSymbolAddress((void**)&a1l,  g_a1l);
    cudaGetSymbolAddress((void**)&s1h,  g_s1h);
    cudaGetSymbolAddress((void**)&s1l,  g_s1l);
    cudaGetSymbolAddress((void**)&s2h,  g_s2h);
    cudaGetSymbolAddress((void**)&s2l,  g_s2l);
    cudaGetSymbolAddress((void**)&t2,   g_t2);
    cudaGetSymbolAddress((void**)&bc1,  g_bc1);
    cudaGetSymbolAddress((void**)&bc2,  g_bc2);
    cudaGetSymbolAddress((void**)&zero, g_zero);

    cudaFuncSetAttribute(gemm_w<false, false, true>, cudaFuncAttributeMaxDynamicSharedMemorySize, GDSM);
    cudaFuncSetAttribute(gemm_w<false, true, false>, cudaFuncAttributeMaxDynamicSharedMemorySize, GDSM);
    cudaFuncSetAttribute(gemm_w<false, true, true>,  cudaFuncAttributeMaxDynamicSharedMemorySize, GDSM);
    cudaFuncSetAttribute(gemm_w<true, true, true>,   cudaFuncAttributeMaxDynamicSharedMemorySize, GDSM);
    cudaFuncSetAttribute(fused_w,                    cudaFuncAttributeMaxDynamicSharedMemorySize, FDSM);

    // --- One-time conversions ---
    conv_T<<<dim3(32, 32, 6), 256>>>(Wv,  wv_h, wv_l);
    conv_T<<<dim3(32, 32, 6), 256>>>(Wo,  wo_h, wo_l);
    conv_T<<<dim3(32, 32, 5), 256>>>(fbW, fb_h, fb_l);
    conv_gT<<<dim3(16, 64, 6), 256>>>(We, we_h, we_l);
    conv_gT<<<dim3(16, 64, 6), 256>>>(Wi, wi_h, wi_l);
    conv_act<<<6 * M1 / 4 / 256, 256>>>(Wlat, s1h, s1l);
    conv_act<<<(int)(BD / 4 / 256), 256>>>(x, a1h, a1l);

    // --- Combo precompute: W_combo = Wlat @ Wv @ Wo ; b_combo ---
    dim3 gridC(8, 4, 6);    // 1024 rows / 256
    gemm_w<false, false, true><<<gridC, 256, GDSM>>>(s1h, s1l, wv_h, wv_l,
        zero, nullptr, s2h, s2l, M1, M1, 0, M1);
    gemm_w<false, true, false><<<gridC, 256, GDSM>>>(s2h, s2l, wo_h, wo_l,
        zero, t2, nullptr, nullptr, M1, M1, 0, M1);
    conv_T<<<dim3(32, 32, 6), 256>>>(t2, wc_h, wc_l);
    bias_combo<<<dim3(4, 6), 256>>>(blat, Wv, bv, bc1);
    bias_combo<<<dim3(4, 6), 256>>>(bc1, Wo, bo, bc2);

    const size_t WL_STRIDE = (size_t)NMC * Hh * Hh;
    dim3 gridG(Dd / 128, Bsz / 256, 1);   // 8 x 64
    dim3 gridF(Dd / 64,  Bsz / 256);      // 16 x 64

    for (int l = 0; l < Lc; l++) {
        fused_w<<<gridF, 256, FDSM>>>(a1h, a1l,
            we_h + (size_t)l * M1, we_l + (size_t)l * M1,
            wi_h + (size_t)l * M1, wi_l + (size_t)l * M1,
            be + l * Dd, bi + l * Dd, Wl + l * WL_STRIDE, bl + l * Dd,
            a0h, a0l);
        gemm_w<false, true, true><<<gridG, 256, GDSM>>>(a0h, a0l,
            wc_h + (size_t)l * M1, wc_l + (size_t)l * M1,
            bc2 + (size_t)l * Dd, out + (size_t)l * BD, a1h, a1l,
            0, 0, 0, 0);
    }

    int p = 1;
    for (int i = 0; i < Lc - 1; i++) {
        int idx = Lc - 2 - i;
        bf16* sh = p ? a1h : a0h;
        bf16* sl = p ? a1l : a0l;
        bf16* dh = p ? a0h : a1h;
        bf16* dl = p ? a0l : a1l;
        gemm_w<true, true, true><<<gridG, 256, GDSM>>>(sh, sl,
            fb_h + (size_t)i * M1, fb_l + (size_t)i * M1,
            fbb + i * Dd, out + (size_t)idx * BD, dh, dl,
            0, 0, 0, 0);
        p ^= 1;
    }
}

// round 8
// speedup vs baseline: 1.1854x; 1.1854x over previous
#include <cuda_runtime.h>
#include <cuda_bf16.h>
#include <mma.h>
#include <cstdint>

using namespace nvcuda;
typedef __nv_bfloat16  bf16;
typedef __nv_bfloat162 bf162;

// Problem constants
#define Bsz 16384
#define Dd  1024
#define Lc  6
#define NMC 64
#define Hh  16
#define M1  (1024 * 1024)
#define BD  ((size_t)Bsz * Dd)

// Tiling: block 128x128 (generic) / 128x64 (fused), 4 warps, occ 2, 2-stage
#define BK   32
#define LDK  40
#define MATB (128 * LDK * 2)
#define GSTGB (4 * MATB)                        // 40960 B/stage
#define FSTGB (2 * MATB + 4 * (64 * LDK * 2))   // 40960 B/stage
#define GDSM (2 * GSTGB)
#define FDSM (2 * FSTGB)
#define NKT  (Dd / BK)

// ---------------------------------------------------------------------------
// Persistent buffers
// ---------------------------------------------------------------------------
__device__ bf16 g_wc_h [6 * M1], g_wc_l [6 * M1];   // combo weights, [n][k]
__device__ bf16 g_wv_h [6 * M1], g_wv_l [6 * M1];
__device__ bf16 g_wo_h [6 * M1], g_wo_l [6 * M1];
__device__ bf16 g_fb_h [5 * M1], g_fb_l [5 * M1];
__device__ bf16 g_we_h [6 * M1], g_we_l [6 * M1];   // gathered [n=m*16+h][k=d]
__device__ bf16 g_wi_h [6 * M1], g_wi_l [6 * M1];
__device__ bf16 g_s1h[6 * M1], g_s1l[6 * M1];
__device__ bf16 g_s2h[6 * M1], g_s2l[6 * M1];
__device__ float g_t2[6 * M1];
__device__ float g_bc1[6 * Dd], g_bc2[6 * Dd];
__device__ float g_zero[Dd];
__device__ bf16 g_a0h[BD], g_a0l[BD], g_a1h[BD], g_a1l[BD];

__device__ __forceinline__ void split1(float v, bf16* h, bf16* l) {
    bf16 hh = __float2bfloat16(v);
    *h = hh;
    *l = __float2bfloat16(v - __bfloat162float(hh));
}

__device__ __forceinline__ void cp16(void* smem, const void* g) {
    uint32_t s = (uint32_t)__cvta_generic_to_shared(smem);
    asm volatile("cp.async.cg.shared.global [%0], [%1], 16;" :: "r"(s), "l"(g));
}
__device__ __forceinline__ void cp_commit() { asm volatile("cp.async.commit_group;"); }
template <int N>
__device__ __forceinline__ void cp_wait() {
    asm volatile("cp.async.wait_group %0;" :: "n"(N));
}

// ---------------------------------------------------------------------------
// Conversion kernels
// ---------------------------------------------------------------------------
__global__ void conv_T(const float* __restrict__ src, bf16* __restrict__ hi,
                       bf16* __restrict__ lo) {
    __shared__ float t[32][33];
    const int l = blockIdx.z;
    const int k0 = blockIdx.y * 32, n0 = blockIdx.x * 32;
    const float* S = src + (size_t)l * M1;
    const int r = threadIdx.x >> 5, c = threadIdx.x & 31;
    #pragma unroll
    for (int i = 0; i < 4; i++)
        t[r + i * 8][c] = S[(size_t)(k0 + r + i * 8) * Dd + n0 + c];
    __syncthreads();
    bf16* H = hi + (size_t)l * M1;
    bf16* L = lo + (size_t)l * M1;
    #pragma unroll
    for (int i = 0; i < 4; i++) {
        bf16 hb, lb; split1(t[c][r + i * 8], &hb, &lb);
        size_t o = (size_t)(n0 + r + i * 8) * Dd + k0 + c;
        H[o] = hb; L[o] = lb;
    }
}

// out[l][m*16+h][d] = src[l][m][d][h]
__global__ void conv_gT(const float* __restrict__ src, bf16* __restrict__ hi,
                        bf16* __restrict__ lo) {
    __shared__ float t[64][17];
    const int d0 = blockIdx.x * 64, m = blockIdx.y, l = blockIdx.z;
    const int tid = threadIdx.x;
    {
        int dd = tid >> 2, h4 = (tid & 3) * 4;
        float4 v = *reinterpret_cast<const float4*>(
            &src[((size_t)(l * NMC + m) * Dd + d0 + dd) * Hh + h4]);
        t[dd][h4] = v.x; t[dd][h4 + 1] = v.y; t[dd][h4 + 2] = v.z; t[dd][h4 + 3] = v.w;
    }
    __syncthreads();
    int h = tid >> 4, cq = tid & 15;
    size_t rowo = (size_t)l * M1 + (size_t)(m * 16 + h) * Dd + d0 + cq * 4;
    #pragma unroll
    for (int j = 0; j < 4; j++) {
        bf16 hb, lb; split1(t[cq * 4 + j][h], &hb, &lb);
        hi[rowo + j] = hb; lo[rowo + j] = lb;
    }
}

__global__ void conv_act(const float* __restrict__ src, bf16* __restrict__ hi,
                         bf16* __restrict__ lo) {
    size_t i = ((size_t)blockIdx.x * blockDim.x + threadIdx.x) * 4;
    float4 v = *reinterpret_cast<const float4*>(src + i);
    bf16 hs[4], ls[4];
    split1(v.x, &hs[0], &ls[0]); split1(v.y, &hs[1], &ls[1]);
    split1(v.z, &hs[2], &ls[2]); split1(v.w, &hs[3], &ls[3]);
    *reinterpret_cast<float2*>(hi + i) = *reinterpret_cast<float2*>(hs);
    *reinterpret_cast<float2*>(lo + i) = *reinterpret_cast<float2*>(ls);
}

// bc[l][j] = sum_i bin[l][i] * W[l][i][j] + badd[l][j]
__global__ void bias_combo(const float* __restrict__ bin, const float* __restrict__ W,
                           const float* __restrict__ badd, float* __restrict__ bc) {
    const int l = blockIdx.y;
    const int j = blockIdx.x * 256 + threadIdx.x;
    const float* Wl = W + (size_t)l * M1;
    const float* bi = bin + (size_t)l * Dd;
    float s = badd[(size_t)l * Dd + j];
    for (int i = 0; i < Dd; i++) s += bi[i] * Wl[(size_t)i * Dd + j];
    bc[(size_t)l * Dd + j] = s;
}

// ---------------------------------------------------------------------------
// GEMM: C = (ACC ? Cf : 0) + A @ W + bias. Block 128x128, warp 64x64, occ 2.
// Single-barrier double-buffered cp.async mainloop. z-batched via strides.
// ---------------------------------------------------------------------------
template <bool ACC, bool WF32, bool WSPLIT>
__global__ __launch_bounds__(128, 2)
void gemm_w(const bf16* __restrict__ Ahi_, const bf16* __restrict__ Alo_,
            const bf16* __restrict__ Whi_, const bf16* __restrict__ Wlo_,
            const float* __restrict__ bias_, float* __restrict__ Cf_,
            bf16* __restrict__ Chi_, bf16* __restrict__ Clo_,
            size_t sA, size_t sW, size_t sB, size_t sC) {
    extern __shared__ char smraw[];
    const int z = blockIdx.z;
    const bf16* Ahi = Ahi_ + (size_t)z * sA;
    const bf16* Alo = Alo_ + (size_t)z * sA;
    const bf16* Whi = Whi_ + (size_t)z * sW;
    const bf16* Wlo = Wlo_ + (size_t)z * sW;
    const float* bias = bias_ + (size_t)z * sB;
    float* Cf = WF32 ? Cf_ + (size_t)z * sC : nullptr;
    bf16* Chi = WSPLIT ? Chi_ + (size_t)z * sC : nullptr;
    bf16* Clo = WSPLIT ? Clo_ + (size_t)z * sC : nullptr;

    const int tid = threadIdx.x, wid = tid >> 5, lane = tid & 31;
    const int wm = wid >> 1, wn = wid & 1;
    const int m0 = blockIdx.y * 128, n0 = blockIdx.x * 128;

    wmma::fragment<wmma::accumulator, 16, 16, 16, float> acc[4][4];
    #pragma unroll
    for (int i = 0; i < 4; i++)
        #pragma unroll
        for (int j = 0; j < 4; j++)
            wmma::fill_fragment(acc[i][j], 0.0f);

    auto load_stage = [&](int st, int kt) {
        bf16* Ah = reinterpret_cast<bf16*>(smraw + st * GSTGB);
        bf16* Al = Ah + 128 * LDK;
        bf16* Bh = Al + 128 * LDK;
        bf16* Bl = Bh + 128 * LDK;
        const int k0 = kt * BK;
        #pragma unroll
        for (int t = 0; t < 4; t++) {
            int item = tid + t * 128;
            int r = item >> 2, c = (item & 3) * 8;
            size_t ga = (size_t)(m0 + r) * Dd + k0 + c;
            size_t gb = (size_t)(n0 + r) * Dd + k0 + c;
            cp16(Ah + r * LDK + c, Ahi + ga);
            cp16(Al + r * LDK + c, Alo + ga);
            cp16(Bh + r * LDK + c, Whi + gb);
            cp16(Bl + r * LDK + c, Wlo + gb);
        }
        cp_commit();
    };

    load_stage(0, 0);
    for (int kt = 0; kt < NKT; kt++) {
        const int st = kt & 1;
        cp_wait<0>();
        __syncthreads();
        if (kt + 1 < NKT) load_stage(st ^ 1, kt + 1);

        bf16* Ah = reinterpret_cast<bf16*>(smraw + st * GSTGB);
        bf16* Al = Ah + 128 * LDK;
        bf16* Bh = Al + 128 * LDK;
        bf16* Bl = Bh + 128 * LDK;
        #pragma unroll
        for (int ks = 0; ks < BK; ks += 16) {
            wmma::fragment<wmma::matrix_b, 16, 16, 16, bf16, wmma::col_major> bh[4], bl[4];
            #pragma unroll
            for (int j = 0; j < 4; j++) {
                wmma::load_matrix_sync(bh[j], &Bh[(wn * 64 + j * 16) * LDK + ks], LDK);
                wmma::load_matrix_sync(bl[j], &Bl[(wn * 64 + j * 16) * LDK + ks], LDK);
            }
            #pragma unroll
            for (int i = 0; i < 4; i++) {
                wmma::fragment<wmma::matrix_a, 16, 16, 16, bf16, wmma::row_major> ah, al;
                wmma::load_matrix_sync(ah, &Ah[(wm * 64 + i * 16) * LDK + ks], LDK);
                wmma::load_matrix_sync(al, &Al[(wm * 64 + i * 16) * LDK + ks], LDK);
                #pragma unroll
                for (int j = 0; j < 4; j++) {
                    wmma::mma_sync(acc[i][j], ah, bh[j], acc[i][j]);
                    wmma::mma_sync(acc[i][j], ah, bl[j], acc[i][j]);
                    wmma::mma_sync(acc[i][j], al, bh[j], acc[i][j]);
                }
            }
        }
    }

    __syncthreads();
    float* patch = reinterpret_cast<float*>(smraw) + wid * 16 * 20;
    const int er = lane >> 1, eh = (lane & 1) * 8;
    #pragma unroll
    for (int i = 0; i < 4; i++) {
        #pragma unroll
        for (int j = 0; j < 4; j++) {
            wmma::store_matrix_sync(patch, acc[i][j], 20, wmma::mem_row_major);
            __syncwarp();
            int gr = m0 + wm * 64 + i * 16 + er;
            int gc = n0 + wn * 64 + j * 16 + eh;
            size_t go = (size_t)gr * Dd + gc;
            float4 b0 = *reinterpret_cast<const float4*>(&bias[gc]);
            float4 b1 = *reinterpret_cast<const float4*>(&bias[gc + 4]);
            float v[8];
            #pragma unroll
            for (int e = 0; e < 8; e++) v[e] = patch[er * 20 + eh + e];
            v[0] += b0.x; v[1] += b0.y; v[2] += b0.z; v[3] += b0.w;
            v[4] += b1.x; v[5] += b1.y; v[6] += b1.z; v[7] += b1.w;
            if (ACC) {
                float4 o0 = *reinterpret_cast<const float4*>(&Cf[go]);
                float4 o1 = *reinterpret_cast<const float4*>(&Cf[go + 4]);
                v[0] += o0.x; v[1] += o0.y; v[2] += o0.z; v[3] += o0.w;
                v[4] += o1.x; v[5] += o1.y; v[6] += o1.z; v[7] += o1.w;
            }
            if (WF32) {
                *reinterpret_cast<float4*>(&Cf[go])     = *reinterpret_cast<float4*>(&v[0]);
                *reinterpret_cast<float4*>(&Cf[go + 4]) = *reinterpret_cast<float4*>(&v[4]);
            }
            if (WSPLIT) {
                bf16 hs[8], ls[8];
                #pragma unroll
                for (int e = 0; e < 8; e++) split1(v[e], &hs[e], &ls[e]);
                *reinterpret_cast<float4*>(&Chi[go]) = *reinterpret_cast<float4*>(hs);
                *reinterpret_cast<float4*>(&Clo[go]) = *reinterpret_cast<float4*>(ls);
            }
            __syncwarp();
        }
    }
}

// ---------------------------------------------------------------------------
// Fused minicolumn kernel: block 128x64, warp 64x32 (e and i), occ 2,
// single-barrier double-buffered mainloop.
// ---------------------------------------------------------------------------
__global__ __launch_bounds__(128, 2)
void fused_w(const bf16* __restrict__ Ahi, const bf16* __restrict__ Alo,
             const bf16* __restrict__ Weh, const bf16* __restrict__ Wel,
             const bf16* __restrict__ Wih, const bf16* __restrict__ Wil,
             const float* __restrict__ be_l, const float* __restrict__ bi_l,
             const float* __restrict__ Wl_l, const float* __restrict__ bl_l,
             bf16* __restrict__ Mhi, bf16* __restrict__ Mlo) {
    extern __shared__ char smraw[];
    __shared__ float swl[1024];
    __shared__ float sbe[64], sbi[64], sbl[64];

    const int tid = threadIdx.x, wid = tid >> 5, lane = tid & 31;
    const int wm = wid >> 1, wn = wid & 1;
    const int m0 = blockIdx.y * 128, n0 = blockIdx.x * 64;

    for (int i = tid; i < 256; i += 128)
        *reinterpret_cast<float4*>(&swl[i * 4]) =
            *reinterpret_cast<const float4*>(&Wl_l[(size_t)n0 * Hh + i * 4]);
    if (tid < 64) {
        sbe[tid] = be_l[n0 + tid];
        sbi[tid] = bi_l[n0 + tid];
        sbl[tid] = bl_l[n0 + tid];
    }

    wmma::fragment<wmma::accumulator, 16, 16, 16, float> ae[4][2], ai[4][2];
    #pragma unroll
    for (int i = 0; i < 4; i++)
        #pragma unroll
        for (int j = 0; j < 2; j++) {
            wmma::fill_fragment(ae[i][j], 0.0f);
            wmma::fill_fragment(ai[i][j], 0.0f);
        }

    auto load_stage = [&](int st, int kt) {
        bf16* Ah = reinterpret_cast<bf16*>(smraw + st * FSTGB);
        bf16* Al = Ah + 128 * LDK;
        bf16* Eh = Al + 128 * LDK;
        bf16* El = Eh + 64 * LDK;
        bf16* Ih = El + 64 * LDK;
        bf16* Il = Ih + 64 * LDK;
        const int k0 = kt * BK;
        #pragma unroll
        for (int t = 0; t < 4; t++) {
            int item = tid + t * 128;
            int r = item >> 2, c = (item & 3) * 8;
            size_t ga = (size_t)(m0 + r) * Dd + k0 + c;
            cp16(Ah + r * LDK + c, Ahi + ga);
            cp16(Al + r * LDK + c, Alo + ga);
        }
        #pragma unroll
        for (int t = 0; t < 2; t++) {
            int item = tid + t * 128;
            int r = item >> 2, c = (item & 3) * 8;
            size_t gb = (size_t)(n0 + r) * Dd + k0 + c;
            cp16(Eh + r * LDK + c, Weh + gb);
            cp16(El + r * LDK + c, Wel + gb);
            cp16(Ih + r * LDK + c, Wih + gb);
            cp16(Il + r * LDK + c, Wil + gb);
        }
        cp_commit();
    };

    load_stage(0, 0);
    for (int kt = 0; kt < NKT; kt++) {
        const int st = kt & 1;
        cp_wait<0>();
        __syncthreads();
        if (kt + 1 < NKT) load_stage(st ^ 1, kt + 1);

        bf16* Ah = reinterpret_cast<bf16*>(smraw + st * FSTGB);
        bf16* Al = Ah + 128 * LDK;
        bf16* Eh = Al + 128 * LDK;
        bf16* El = Eh + 64 * LDK;
        bf16* Ih = El + 64 * LDK;
        bf16* Il = Ih + 64 * LDK;
        #pragma unroll
        for (int ks = 0; ks < BK; ks += 16) {
            wmma::fragment<wmma::matrix_b, 16, 16, 16, bf16, wmma::col_major>
                eh[2], el[2], ih[2], il[2];
            #pragma unroll
            for (int j = 0; j < 2; j++) {
                int nb = (wn * 32 + j * 16) * LDK + ks;
                wmma::load_matrix_sync(eh[j], &Eh[nb], LDK);
                wmma::load_matrix_sync(el[j], &El[nb], LDK);
                wmma::load_matrix_sync(ih[j], &Ih[nb], LDK);
                wmma::load_matrix_sync(il[j], &Il[nb], LDK);
            }
            #pragma unroll
            for (int i = 0; i < 4; i++) {
                wmma::fragment<wmma::matrix_a, 16, 16, 16, bf16, wmma::row_major> ah, al;
                wmma::load_matrix_sync(ah, &Ah[(wm * 64 + i * 16) * LDK + ks], LDK);
                wmma::load_matrix_sync(al, &Al[(wm * 64 + i * 16) * LDK + ks], LDK);
                #pragma unroll
                for (int j = 0; j < 2; j++) {
                    wmma::mma_sync(ae[i][j], ah, eh[j], ae[i][j]);
                    wmma::mma_sync(ae[i][j], ah, el[j], ae[i][j]);
                    wmma::mma_sync(ae[i][j], al, eh[j], ae[i][j]);
                    wmma::mma_sync(ai[i][j], ah, ih[j], ai[i][j]);
                    wmma::mma_sync(ai[i][j], ah, il[j], ai[i][j]);
                    wmma::mma_sync(ai[i][j], al, ih[j], ai[i][j]);
                }
            }
        }
    }

    __syncthreads();
    float* pe = reinterpret_cast<float*>(smraw) + wid * 2 * 16 * 20;
    float* pi = pe + 16 * 20;
    const int er = lane >> 1, eh8 = (lane & 1) * 8;
    #pragma unroll
    for (int i = 0; i < 4; i++) {
        #pragma unroll
        for (int j = 0; j < 2; j++) {
            wmma::store_matrix_sync(pe, ae[i][j], 20, wmma::mem_row_major);
            wmma::store_matrix_sync(pi, ai[i][j], 20, wmma::mem_row_major);
            __syncwarp();
            int ml = wn * 2 + j;
            int gr = m0 + wm * 64 + i * 16 + er;
            float ihv[16];
            #pragma unroll
            for (int h = 0; h < 16; h++)
                ihv[h] = fmaxf(pi[er * 20 + h] + sbi[ml * 16 + h], 0.0f);
            bf16 hs[8], ls[8];
            #pragma unroll
            for (int e = 0; e < 8; e++) {
                int k = eh8 + e;
                float lat = sbl[ml * 16 + k];
                #pragma unroll
                for (int h = 0; h < 16; h++)
                    lat += ihv[h] * swl[ml * 256 + h * 16 + k];
                float ex = fmaxf(pe[er * 20 + k] + sbe[ml * 16 + k], 0.0f);
                split1(fmaxf(ex - lat, 0.0f), &hs[e], &ls[e]);
            }
            size_t go = (size_t)gr * Dd + n0 + ml * 16 + eh8;
            *reinterpret_cast<float4*>(&Mhi[go]) = *reinterpret_cast<float4*>(hs);
            *reinterpret_cast<float4*>(&Mlo[go]) = *reinterpret_cast<float4*>(ls);
            __syncwarp();
        }
    }
}

// ---------------------------------------------------------------------------
// Host orchestration
// ---------------------------------------------------------------------------
extern "C" void kernel_launch(void* const* d_in, const int* in_sizes, int n_in,
                              void* d_out, int out_size) {
    const float* x    = (const float*)d_in[0];
    const float* We   = (const float*)d_in[1];
    const float* be   = (const float*)d_in[2];
    const float* Wi   = (const float*)d_in[3];
    const float* bi   = (const float*)d_in[4];
    const float* Wl   = (const float*)d_in[5];
    const float* bl   = (const float*)d_in[6];
    const float* Wlat = (const float*)d_in[7];
    const float* blat = (const float*)d_in[8];
    const float* Wv   = (const float*)d_in[9];
    const float* bv   = (const float*)d_in[10];
    const float* Wo   = (const float*)d_in[11];
    const float* bo   = (const float*)d_in[12];
    const float* fbW  = (const float*)d_in[13];
    const float* fbb  = (const float*)d_in[14];
    float* out = (float*)d_out;

    bf16 *wc_h, *wc_l, *wv_h, *wv_l, *wo_h, *wo_l, *fb_h, *fb_l;
    bf16 *we_h, *we_l, *wi_h, *wi_l, *a0h, *a0l, *a1h, *a1l;
    bf16 *s1h, *s1l, *s2h, *s2l;
    float *t2, *bc1, *bc2, *zero;
    cudaGetSymbolAddress((void**)&wc_h, g_wc_h);
    cudaGetSymbolAddress((void**)&wc_l, g_wc_l);
    cudaGetSymbolAddress((void**)&wv_h, g_wv_h);
    cudaGetSymbolAddress((void**)&wv_l, g_wv_l);
    cudaGetSymbolAddress((void**)&wo_h, g_wo_h);
    cudaGetSymbolAddress((void**)&wo_l, g_wo_l);
    cudaGetSymbolAddress((void**)&fb_h, g_fb_h);
    cudaGetSymbolAddress((void**)&fb_l, g_fb_l);
    cudaGetSymbolAddress((void**)&we_h, g_we_h);
    cudaGetSymbolAddress((void**)&we_l, g_we_l);
    cudaGetSymbolAddress((void**)&wi_h, g_wi_h);
    cudaGetSymbolAddress((void**)&wi_l, g_wi_l);
    cudaGetSymbolAddress((void**)&a0h,  g_a0h);
    cudaGetSymbolAddress((void**)&a0l,  g_a0l);
    cudaGetSymbolAddress((void**)&a1h,  g_a1h);
    cudaGetSymbolAddress((void**)&a1l,  g_a1l);
    cudaGetSymbolAddress((void**)&s1h,  g_s1h);
    cudaGetSymbolAddress((void**)&s1l,  g_s1l);
    cudaGetSymbolAddress((void**)&s2h,  g_s2h);
    cudaGetSymbolAddress((void**)&s2l,  g_s2l);
    cudaGetSymbolAddress((void**)&t2,   g_t2);
    cudaGetSymbolAddress((void**)&bc1,  g_bc1);
    cudaGetSymbolAddress((void**)&bc2,  g_bc2);
    cudaGetSymbolAddress((void**)&zero, g_zero);

    cudaFuncSetAttribute(gemm_w<false, false, true>, cudaFuncAttributeMaxDynamicSharedMemorySize, GDSM);
    cudaFuncSetAttribute(gemm_w<false, true, false>, cudaFuncAttributeMaxDynamicSharedMemorySize, GDSM);
    cudaFuncSetAttribute(gemm_w<false, true, true>,  cudaFuncAttributeMaxDynamicSharedMemorySize, GDSM);
    cudaFuncSetAttribute(gemm_w<true, true, true>,   cudaFuncAttributeMaxDynamicSharedMemorySize, GDSM);
    cudaFuncSetAttribute(fused_w,                    cudaFuncAttributeMaxDynamicSharedMemorySize, FDSM);

    // --- One-time conversions ---
    conv_T<<<dim3(32, 32, 6), 256>>>(Wv,  wv_h, wv_l);
    conv_T<<<dim3(32, 32, 6), 256>>>(Wo,  wo_h, wo_l);
    conv_T<<<dim3(32, 32, 5), 256>>>(fbW, fb_h, fb_l);
    conv_gT<<<dim3(16, 64, 6), 256>>>(We, we_h, we_l);
    conv_gT<<<dim3(16, 64, 6), 256>>>(Wi, wi_h, wi_l);
    conv_act<<<6 * M1 / 4 / 256, 256>>>(Wlat, s1h, s1l);
    conv_act<<<(int)(BD / 4 / 256), 256>>>(x, a1h, a1l);

    // --- Combo precompute: W_combo = Wlat @ Wv @ Wo ; b_combo ---
    dim3 gridC(8, 8, 6);
    gemm_w<false, false, true><<<gridC, 128, GDSM>>>(s1h, s1l, wv_h, wv_l,
        zero, nullptr, s2h, s2l, M1, M1, 0, M1);
    gemm_w<false, true, false><<<gridC, 128, GDSM>>>(s2h, s2l, wo_h, wo_l,
        zero, t2, nullptr, nullptr, M1, M1, 0, M1);
    conv_T<<<dim3(32, 32, 6), 256>>>(t2, wc_h, wc_l);
    bias_combo<<<dim3(4, 6), 256>>>(blat, Wv, bv, bc1);
    bias_combo<<<dim3(4, 6), 256>>>(bc1, Wo, bo, bc2);

    const size_t WL_STRIDE = (size_t)NMC * Hh * Hh;
    dim3 gridG(Dd / 128, Bsz / 128, 1);   // 8 x 128
    dim3 gridF(Dd / 64,  Bsz / 128);      // 16 x 128

    for (int l = 0; l < Lc; l++) {
        fused_w<<<gridF, 128, FDSM>>>(a1h, a1l,
            we_h + (size_t)l * M1, we_l + (size_t)l * M1,
            wi_h + (size_t)l * M1, wi_l + (size_t)l * M1,
            be + l * Dd, bi + l * Dd, Wl + l * WL_STRIDE, bl + l * Dd,
            a0h, a0l);
        gemm_w<false, true, true><<<gridG, 128, GDSM>>>(a0h, a0l,
            wc_h + (size_t)l * M1, wc_l + (size_t)l * M1,
            bc2 + (size_t)l * Dd, out + (size_t)l * BD, a1h, a1l,
            0, 0, 0, 0);
    }

    int p = 1;
    for (int i = 0; i < Lc - 1; i++) {
        int idx = Lc - 2 - i;
        bf16* sh = p ? a1h : a0h;
        bf16* sl = p ? a1l : a0l;
        bf16* dh = p ? a0h : a1h;
        bf16* dl = p ? a0l : a1l;
        gemm_w<true, true, true><<<gridG, 128, GDSM>>>(sh, sl,
            fb_h + (size_t)i * M1, fb_l + (size_t)i * M1,
            fbb + i * Dd, out + (size_t)idx * BD, dh, dl,
            0, 0, 0, 0);
        p ^= 1;
    }
}